// round 16
// baseline (speedup 1.0000x reference)
#include <cuda_runtime.h>
#include <cuda_fp16.h>
#include <cstdint>

#define NROWS   262144
#define NSEG    1024
#define HID     256
#define KDIM    256

// ---------------- scratch (device globals: no allocations allowed) ----------
__device__ float  g_scores[NROWS];
__device__ uint4  g_bfrag[8192];              // B in mma-fragment order (128KB)
__device__ __half g_xh[(size_t)NROWS * KDIM]; // fp16 copy of x
__device__ int    g_segstart[NSEG + 1];
__device__ int    g_tflag[2048];              // per-tile score-ready flags

// ---------------- helpers ----------------------------------------------------
static __device__ __forceinline__ uint32_t smem_u32(const void* p) {
    uint32_t a;
    asm("{ .reg .u64 t; cvta.to.shared.u64 t, %1; cvt.u32.u64 %0, t; }"
        : "=r"(a) : "l"(p));
    return a;
}

static __device__ __forceinline__ void ldsm_x4(uint32_t a, uint32_t& r0, uint32_t& r1,
                                               uint32_t& r2, uint32_t& r3) {
    asm volatile("ldmatrix.sync.aligned.m8n8.x4.shared.b16 {%0,%1,%2,%3}, [%4];"
                 : "=r"(r0), "=r"(r1), "=r"(r2), "=r"(r3) : "r"(a));
}

static __device__ __forceinline__ void mma_f16(float* c,
                                               uint32_t a0, uint32_t a1, uint32_t a2, uint32_t a3,
                                               uint32_t b0, uint32_t b1) {
    asm volatile("mma.sync.aligned.m16n8k16.row.col.f32.f16.f16.f32 "
                 "{%0,%1,%2,%3}, {%4,%5,%6,%7}, {%8,%9}, {%0,%1,%2,%3};"
                 : "+f"(c[0]), "+f"(c[1]), "+f"(c[2]), "+f"(c[3])
                 : "r"(a0), "r"(a1), "r"(a2), "r"(a3), "r"(b0), "r"(b1));
}

static __device__ __forceinline__ uint32_t pack_h2(float a, float b) {
    __half2 h = __floats2half2_rn(a, b);
    return *(uint32_t*)&h;
}

static __device__ __forceinline__ void cp16(uint32_t dst, const void* src) {
    asm volatile("cp.async.cg.shared.global [%0], [%1], 16;"
                 :: "r"(dst), "l"(src) : "memory");
}
#define CP_COMMIT() asm volatile("cp.async.commit_group;" ::: "memory")
#define CP_WAIT(N)  asm volatile("cp.async.wait_group %0;" :: "n"(N) : "memory")

// ---------------- kernel 1: B fragments + boundary scan + flag reset ---------
__global__ void k_prep(const float* __restrict__ W1,
                       const void* __restrict__ batch_raw) {
    int tid = threadIdx.x;
    if (blockIdx.x < 4) {
        __shared__ char fs[32768];
        uint32_t sb = smem_u32(fs);
        int wid = tid >> 5, lid = tid & 31;
        int ch = blockIdx.x;
        #pragma unroll
        for (int it = 0; it < 8; it++) {
            int idx = tid + it * 256;
            int nl = idx & 63, c = idx >> 6;
            int n = ch * 64 + nl;
            uint32_t h[4];
            #pragma unroll
            for (int qq = 0; qq < 4; qq++) {
                float v0 = W1[(c * 8 + 2 * qq) * 256 + n];
                float v1 = W1[(c * 8 + 2 * qq + 1) * 256 + n];
                h[qq] = pack_h2(v0, v1);
            }
            *(uint4*)(fs + nl * 512 + ((c ^ (nl & 7)) << 4)) =
                make_uint4(h[0], h[1], h[2], h[3]);
        }
        __syncthreads();
        int nw = wid & 1;
        int j = lid >> 3, r8 = lid & 7;
        int bc0 = j & 1;
        int nloc = nw * 32 + ((j >> 1) << 3) + r8;
        int bnm = nloc & 7;
        uint32_t boff0 = nloc * 512;
        #pragma unroll
        for (int i = 0; i < 4; i++) {
            int ks = (wid >> 1) * 4 + i;
            uint32_t so = (uint32_t)(((2 * ks + bc0) ^ bnm) << 4);
            uint32_t b0[4], b1r[4];
            ldsm_x4(sb + boff0 + so,        b0[0], b0[1], b0[2], b0[3]);
            ldsm_x4(sb + boff0 + 8192 + so, b1r[0], b1r[1], b1r[2], b1r[3]);
            size_t base = ((size_t)(nw * 4 + ch) * 16 + ks) * 64;
            g_bfrag[base + lid]      = make_uint4(b0[0], b0[1], b0[2], b0[3]);
            g_bfrag[base + 32 + lid] = make_uint4(b1r[0], b1r[1], b1r[2], b1r[3]);
        }
        return;
    }
    if (blockIdx.x == 4) {
        for (int i = tid; i < 2048; i += 256) g_tflag[i] = 0;
    }
    const int* b32 = (const int*)batch_raw;
    const long long* b64 = (const long long*)batch_raw;
    bool is64 = (b32[NROWS - 1] == 0) && (b32[NROWS - 3] == 0) &&
                (b32[NROWS - 5] == 0) && (b32[NROWS - 7] == 0);
    int gt = (blockIdx.x - 4) * 256 + tid;
    #pragma unroll
    for (int q = 0; q < 4; q++) {
        int i = gt * 4 + q;
        if (i >= NROWS) break;
        int v = is64 ? (int)b64[i] : b32[i];
        if (i == 0) {
            for (int g = 0; g <= v; g++) g_segstart[g] = 0;
        }
        if (i == NROWS - 1) {
            for (int g = v + 1; g <= NSEG; g++) g_segstart[g] = NROWS;
        } else {
            int v1 = is64 ? (int)b64[i + 1] : b32[i + 1];
            for (int g = v + 1; g <= v1; g++) g_segstart[g] = i + 1;
        }
    }
}

// ---------------- kernel 2: fused scores + pool ------------------------------
// bid%3 in {0,1}: score tile 2*(bid/3)+(bid%3). bid%3==2: pool segment bid/3.
// scores smem layout (within 78848):
#define SM_A   0          // 128 x 256 fp16, swizzled           (65536)
#define SM_SC  65536      // 128 f32 partial scores             (512)
#define SM_B1  66048      // 256 f32                            (1024)
#define SM_W2  67072      // 256 f32                            (1024)
// pool smem layout: [0,32768) xbuf0, [32768,65536) xbuf1
#define P_WB   65536
#define P_RED  69632
#define P_ACC  70656
#define SMEM_MAIN_TOTAL 78848

__global__ void __launch_bounds__(256, 2)
k_main(const float* __restrict__ x, const float* __restrict__ b1,
       const float* __restrict__ W2, const float* __restrict__ b2,
       float* __restrict__ out) {
    extern __shared__ char smem[];
    uint32_t sb = smem_u32(smem);
    int tid = threadIdx.x, wid = tid >> 5, lid = tid & 31;
    int role = blockIdx.x % 3, q = blockIdx.x / 3;

    if (role < 2) {
        // ================= scores tile =================
        int tile = q * 2 + role;
        size_t rowbase = (size_t)tile * 128;
        int mw = wid & 3, nw = wid >> 2;          // warp grid: 4 (M) x 2 (N)

        if (tid < 128) ((float*)(smem + SM_SC))[tid] = 0.f;
        ((float*)(smem + SM_B1))[tid] = b1[tid];
        ((float*)(smem + SM_W2))[tid] = W2[tid];

        // stage A tile: f32 -> fp16, swizzled; also write g_xh
        {
            const float4* xp = (const float4*)(x + rowbase * 256);
            uint4* xh_out = (uint4*)(g_xh + rowbase * 256);
            #pragma unroll
            for (int i = 0; i < 16; i++) {
                int cid = tid + i * 256;
                int row = cid >> 5, c = cid & 31;
                float4 v0 = __ldg(&xp[row * 64 + c * 2]);
                float4 v1 = __ldg(&xp[row * 64 + c * 2 + 1]);
                uint4 hv;
                hv.x = pack_h2(v0.x, v0.y);
                hv.y = pack_h2(v0.z, v0.w);
                hv.z = pack_h2(v1.x, v1.y);
                hv.w = pack_h2(v1.z, v1.w);
                uint32_t off = row * 512 + ((c ^ (row & 7)) << 4);
                *(uint4*)(smem + SM_A + off) = hv;
                xh_out[row * 32 + c] = hv;
            }
        }

        int g = lid >> 2, t = lid & 3, r8 = lid & 7, j = lid >> 3;
        int arow = mw * 32 + (j & 1) * 8 + r8;
        uint32_t aoff0 = SM_A + arow * 512;
        int arm = arow & 7, ac0 = j >> 1;

        const float* smB1 = (const float*)(smem + SM_B1);
        const float* smW2 = (const float*)(smem + SM_W2);
        float part[4] = {0.f, 0.f, 0.f, 0.f};

        __syncthreads();

        for (int ch = 0; ch < 4; ch++) {
            const uint4* bp = g_bfrag + ((size_t)(nw * 4 + ch) * 16) * 64 + lid;

            float acc[2][4][4];
            #pragma unroll
            for (int a = 0; a < 2; a++)
                #pragma unroll
                for (int b = 0; b < 4; b++)
                    #pragma unroll
                    for (int cc = 0; cc < 4; cc++) acc[a][b][cc] = 0.f;

            #pragma unroll 8
            for (int ks = 0; ks < 16; ks++) {
                uint32_t sa = (uint32_t)(((2 * ks + ac0) ^ arm) << 4);
                uint32_t a0[4], a1[4];
                ldsm_x4(sb + aoff0 + sa,        a0[0], a0[1], a0[2], a0[3]);
                ldsm_x4(sb + aoff0 + 8192 + sa, a1[0], a1[1], a1[2], a1[3]);
                uint4 q0 = __ldg(bp + ks * 64);
                uint4 q1 = __ldg(bp + ks * 64 + 32);

                mma_f16(acc[0][0], a0[0], a0[1], a0[2], a0[3], q0.x, q0.y);
                mma_f16(acc[0][1], a0[0], a0[1], a0[2], a0[3], q0.z, q0.w);
                mma_f16(acc[0][2], a0[0], a0[1], a0[2], a0[3], q1.x, q1.y);
                mma_f16(acc[0][3], a0[0], a0[1], a0[2], a0[3], q1.z, q1.w);
                mma_f16(acc[1][0], a1[0], a1[1], a1[2], a1[3], q0.x, q0.y);
                mma_f16(acc[1][1], a1[0], a1[1], a1[2], a1[3], q0.z, q0.w);
                mma_f16(acc[1][2], a1[0], a1[1], a1[2], a1[3], q1.x, q1.y);
                mma_f16(acc[1][3], a1[0], a1[1], a1[2], a1[3], q1.z, q1.w);
            }

            int colb = ch * 64 + nw * 32 + 2 * t;
            #pragma unroll
            for (int nt = 0; nt < 4; nt++) {
                float bv0 = smB1[colb + nt * 8],     bv1 = smB1[colb + nt * 8 + 1];
                float wv0 = smW2[colb + nt * 8],     wv1 = smW2[colb + nt * 8 + 1];
                #pragma unroll
                for (int mt = 0; mt < 2; mt++) {
                    part[mt * 2 + 0] += fmaxf(acc[mt][nt][0] + bv0, 0.f) * wv0
                                      + fmaxf(acc[mt][nt][1] + bv1, 0.f) * wv1;
                    part[mt * 2 + 1] += fmaxf(acc[mt][nt][2] + bv0, 0.f) * wv0
                                      + fmaxf(acc[mt][nt][3] + bv1, 0.f) * wv1;
                }
            }
        }

        #pragma unroll
        for (int p = 0; p < 4; p++) {
            part[p] += __shfl_xor_sync(0xffffffffu, part[p], 1);
            part[p] += __shfl_xor_sync(0xffffffffu, part[p], 2);
        }
        if (t == 0) {
            float* sc = (float*)(smem + SM_SC);
            atomicAdd(&sc[mw * 32 + g],      part[0]);
            atomicAdd(&sc[mw * 32 + 8 + g],  part[1]);
            atomicAdd(&sc[mw * 32 + 16 + g], part[2]);
            atomicAdd(&sc[mw * 32 + 24 + g], part[3]);
        }
        __syncthreads();
        if (tid < 128)
            g_scores[rowbase + tid] = ((float*)(smem + SM_SC))[tid] + __ldg(b2);
        __threadfence();                          // release all tile writes
        __syncthreads();
        if (tid == 0) atomicExch(&g_tflag[tile], 1);
        return;
    }

    // ================= pool segment =================
    {
        float* wbuf = (float*)(smem + P_WB);
        float* red  = (float*)(smem + P_RED);
        float* accs = (float*)(smem + P_ACC);     // [8][256]
        int g = q, t = tid;
        int rg = t >> 5, cl = t & 31;
        int s0 = g_segstart[g], s1 = g_segstart[g + 1];

        // wait for all tiles covering this segment
        if (s1 > s0) {
            if (t == 0) {
                int first = s0 >> 7, last = (s1 - 1) >> 7;
                for (int tI = first; tI <= last; tI++)
                    while (*(volatile int*)&g_tflag[tI] == 0) __nanosleep(200);
            }
            __syncthreads();
            __threadfence();                      // acquire
        }

        float m = 0.f;
        for (int i = s0 + t; i < s1; i += 256) m = fmaxf(m, __ldcg(&g_scores[i]));
        red[t] = m; __syncthreads();
        #pragma unroll
        for (int st = 128; st > 0; st >>= 1) {
            if (t < st) red[t] = fmaxf(red[t], red[t + st]);
            __syncthreads();
        }
        m = red[0]; __syncthreads();

        float den = 0.f;
        float ac[8] = {0.f, 0.f, 0.f, 0.f, 0.f, 0.f, 0.f, 0.f};
        const char* xbytes = (const char*)g_xh;

        for (int base = s0; base < s1; base += 1024) {
            int n = min(1024, s1 - base);
            for (int i = t; i < n; i += 256) {
                float e = __expf(__ldcg(&g_scores[base + i]) - m);
                wbuf[i] = e;
                den += e;
            }
            __syncthreads();

            int nsub = (n + 63) >> 6;
            {
                int cnt = min(64, n) * 32;
                const char* src = xbytes + (size_t)base * 512;
                for (int idx = t; idx < cnt; idx += 256)
                    cp16(sb + idx * 16, src + (size_t)idx * 16);
                CP_COMMIT();
            }
            for (int s = 0; s < nsub; s++) {
                if (s > 0) __syncthreads();
                if (s + 1 < nsub) {
                    int r0n = (s + 1) * 64;
                    int cnt = min(64, n - r0n) * 32;
                    const char* src = xbytes + (size_t)(base + r0n) * 512;
                    uint32_t dst = sb + ((s + 1) & 1) * 32768;
                    for (int idx = t; idx < cnt; idx += 256)
                        cp16(dst + idx * 16, src + (size_t)idx * 16);
                    CP_COMMIT();
                    CP_WAIT(1);
                } else {
                    CP_WAIT(0);
                }
                __syncthreads();

                int r0 = s * 64;
                int cnt = min(64, n - r0);
                uint32_t buf = sb + (s & 1) * 32768 + cl * 16;
                for (int i = rg; i < cnt; i += 8) {
                    float w = wbuf[r0 + i];
                    uint32_t q0, q1, q2, q3;
                    asm volatile("ld.shared.v4.u32 {%0,%1,%2,%3}, [%4];"
                                 : "=r"(q0), "=r"(q1), "=r"(q2), "=r"(q3)
                                 : "r"(buf + (uint32_t)i * 512));
                    float2 p;
                    p = __half22float2(*(__half2*)&q0);
                    ac[0] = fmaf(p.x, w, ac[0]); ac[1] = fmaf(p.y, w, ac[1]);
                    p = __half22float2(*(__half2*)&q1);
                    ac[2] = fmaf(p.x, w, ac[2]); ac[3] = fmaf(p.y, w, ac[3]);
                    p = __half22float2(*(__half2*)&q2);
                    ac[4] = fmaf(p.x, w, ac[4]); ac[5] = fmaf(p.y, w, ac[5]);
                    p = __half22float2(*(__half2*)&q3);
                    ac[6] = fmaf(p.x, w, ac[6]); ac[7] = fmaf(p.y, w, ac[7]);
                }
            }
            __syncthreads();
        }

        red[t] = den; __syncthreads();
        #pragma unroll
        for (int st = 128; st > 0; st >>= 1) {
            if (t < st) red[t] += red[t + st];
            __syncthreads();
        }
        den = red[0] + 1e-9f;
        __syncthreads();

        #pragma unroll
        for (int h = 0; h < 8; h++) accs[rg * 256 + cl * 8 + h] = ac[h];
        __syncthreads();
        float s = 0.f;
        #pragma unroll
        for (int r = 0; r < 8; r++) s += accs[r * 256 + t];
        out[g * 256 + t] = s / den;
    }
}

// ---------------- launch ----------------------------------------------------
extern "C" void kernel_launch(void* const* d_in, const int* in_sizes, int n_in,
                              void* d_out, int out_size) {
    const float* x = 0; const float* W1 = 0; const float* b1 = 0;
    const float* W2 = 0; const float* b2 = 0; const void* batch = 0;
    for (int i = 0; i < n_in; i++) {
        switch (in_sizes[i]) {
            case 67108864: x = (const float*)d_in[i]; break;
            case 65536:    W1 = (const float*)d_in[i]; break;
            case 262144:   batch = d_in[i]; break;
            case 1:        b2 = (const float*)d_in[i]; break;
            case 256:
                if (!b1) b1 = (const float*)d_in[i];
                else     W2 = (const float*)d_in[i];
                break;
            default: break;
        }
    }
    if (!x)     x     = (const float*)d_in[0];
    if (!W1)    W1    = (const float*)d_in[1];
    if (!b1)    b1    = (const float*)d_in[2];
    if (!W2)    W2    = (const float*)d_in[3];
    if (!b2)    b2    = (const float*)d_in[4];
    if (!batch) batch = d_in[5];

    cudaFuncSetAttribute(k_main, cudaFuncAttributeMaxDynamicSharedMemorySize,
                         SMEM_MAIN_TOTAL);

    k_prep<<<260, 256>>>(W1, batch);
    k_main<<<3072, 256, SMEM_MAIN_TOTAL>>>(x, b1, W2, b2, (float*)d_out);
}

// round 17
// speedup vs baseline: 1.2464x; 1.2464x over previous
#include <cuda_runtime.h>
#include <cuda_fp16.h>
#include <cstdint>

#define NROWS   262144
#define NSEG    1024
#define HID     256
#define KDIM    256

// ---------------- scratch (device globals: no allocations allowed) ----------
__device__ float  g_scores[NROWS];
__device__ uint4  g_bfrag[8192];              // B in mma-fragment order (128KB)
__device__ __half g_xh[(size_t)NROWS * KDIM]; // fp16 copy of x (written by k_scores)
__device__ int    g_segstart[NSEG + 1];

// ---------------- helpers ----------------------------------------------------
static __device__ __forceinline__ uint32_t smem_u32(const void* p) {
    uint32_t a;
    asm("{ .reg .u64 t; cvta.to.shared.u64 t, %1; cvt.u32.u64 %0, t; }"
        : "=r"(a) : "l"(p));
    return a;
}

static __device__ __forceinline__ void ldsm_x4(uint32_t a, uint32_t& r0, uint32_t& r1,
                                               uint32_t& r2, uint32_t& r3) {
    asm volatile("ldmatrix.sync.aligned.m8n8.x4.shared.b16 {%0,%1,%2,%3}, [%4];"
                 : "=r"(r0), "=r"(r1), "=r"(r2), "=r"(r3) : "r"(a));
}

static __device__ __forceinline__ void mma_f16(float* c,
                                               uint32_t a0, uint32_t a1, uint32_t a2, uint32_t a3,
                                               uint32_t b0, uint32_t b1) {
    asm volatile("mma.sync.aligned.m16n8k16.row.col.f32.f16.f16.f32 "
                 "{%0,%1,%2,%3}, {%4,%5,%6,%7}, {%8,%9}, {%0,%1,%2,%3};"
                 : "+f"(c[0]), "+f"(c[1]), "+f"(c[2]), "+f"(c[3])
                 : "r"(a0), "r"(a1), "r"(a2), "r"(a3), "r"(b0), "r"(b1));
}

static __device__ __forceinline__ uint32_t pack_h2(float a, float b) {
    __half2 h = __floats2half2_rn(a, b);
    return *(uint32_t*)&h;
}

static __device__ __forceinline__ void cp16(uint32_t dst, const void* src) {
    asm volatile("cp.async.cg.shared.global [%0], [%1], 16;"
                 :: "r"(dst), "l"(src) : "memory");
}
#define CP_COMMIT() asm volatile("cp.async.commit_group;" ::: "memory")
#define CP_WAIT(N)  asm volatile("cp.async.wait_group %0;" :: "n"(N) : "memory")

// ---------------- kernel 1: B fragments (from W1) + boundary scan ------------
// blocks 0..3: build g_bfrag directly from W1.
// blocks 4..1027: bounds, 1 row per thread (max parallelism).
__global__ void k_prep(const float* __restrict__ W1,
                       const void* __restrict__ batch_raw) {
    int tid = threadIdx.x;
    if (blockIdx.x < 4) {
        __shared__ char fs[32768];
        uint32_t sb = smem_u32(fs);
        int wid = tid >> 5, lid = tid & 31;
        int ch = blockIdx.x;
        #pragma unroll
        for (int it = 0; it < 8; it++) {
            int idx = tid + it * 256;             // 0..2047
            int nl = idx & 63, c = idx >> 6;
            int n = ch * 64 + nl;
            uint32_t h[4];
            #pragma unroll
            for (int qq = 0; qq < 4; qq++) {
                float v0 = W1[(c * 8 + 2 * qq) * 256 + n];
                float v1 = W1[(c * 8 + 2 * qq + 1) * 256 + n];
                h[qq] = pack_h2(v0, v1);
            }
            *(uint4*)(fs + nl * 512 + ((c ^ (nl & 7)) << 4)) =
                make_uint4(h[0], h[1], h[2], h[3]);
        }
        __syncthreads();
        int nw = wid & 1;
        int j = lid >> 3, r8 = lid & 7;
        int bc0 = j & 1;
        int nloc = nw * 32 + ((j >> 1) << 3) + r8;
        int bnm = nloc & 7;
        uint32_t boff0 = nloc * 512;
        #pragma unroll
        for (int i = 0; i < 4; i++) {
            int ks = (wid >> 1) * 4 + i;
            uint32_t so = (uint32_t)(((2 * ks + bc0) ^ bnm) << 4);
            uint32_t b0[4], b1r[4];
            ldsm_x4(sb + boff0 + so,        b0[0], b0[1], b0[2], b0[3]);
            ldsm_x4(sb + boff0 + 8192 + so, b1r[0], b1r[1], b1r[2], b1r[3]);
            size_t base = ((size_t)(nw * 4 + ch) * 16 + ks) * 64;
            g_bfrag[base + lid]      = make_uint4(b0[0], b0[1], b0[2], b0[3]);
            g_bfrag[base + 32 + lid] = make_uint4(b1r[0], b1r[1], b1r[2], b1r[3]);
        }
        return;
    }
    const int* b32 = (const int*)batch_raw;
    const long long* b64 = (const long long*)batch_raw;
    bool is64 = (b32[NROWS - 1] == 0) && (b32[NROWS - 3] == 0) &&
                (b32[NROWS - 5] == 0) && (b32[NROWS - 7] == 0);
    int i = (blockIdx.x - 4) * 256 + tid;         // one row per thread
    if (i >= NROWS) return;
    int v = is64 ? (int)b64[i] : b32[i];
    if (i == 0) {
        for (int g = 0; g <= v; g++) g_segstart[g] = 0;
    }
    if (i == NROWS - 1) {
        for (int g = v + 1; g <= NSEG; g++) g_segstart[g] = NROWS;
    } else {
        int v1 = is64 ? (int)b64[i + 1] : b32[i + 1];
        for (int g = v + 1; g <= v1; g++) g_segstart[g] = i + 1;
    }
}

// ---------------- kernel 2: scores, barrier-free mainloop (LOCKED) -----------
#define SM_A   0          // 128 x 256 fp16, swizzled           (65536)
#define SM_SC  65536      // 128 f32 partial scores             (512)
#define SM_B1  66048      // 256 f32                            (1024)
#define SM_W2  67072      // 256 f32                            (1024)
#define SMEM_SCORES_TOTAL 68096

__global__ void __launch_bounds__(256, 2)
k_scores(const float* __restrict__ x, const float* __restrict__ b1,
         const float* __restrict__ W2, const float* __restrict__ b2) {
    extern __shared__ char smem[];
    uint32_t sb = smem_u32(smem);
    int tid = threadIdx.x, wid = tid >> 5, lid = tid & 31;
    size_t rowbase = (size_t)blockIdx.x * 128;
    int mw = wid & 3, nw = wid >> 2;              // warp grid: 4 (M) x 2 (N)

    // stage constants, zero score accumulator
    if (tid < 128) ((float*)(smem + SM_SC))[tid] = 0.f;
    ((float*)(smem + SM_B1))[tid] = b1[tid];
    ((float*)(smem + SM_W2))[tid] = W2[tid];

    // ---- stage A tile: 128x256 f32 -> fp16, swizzled; also write g_xh ----
    {
        const float4* xp = (const float4*)(x + rowbase * 256);
        uint4* xh_out = (uint4*)(g_xh + rowbase * 256);
        #pragma unroll
        for (int i = 0; i < 16; i++) {
            int cid = tid + i * 256;              // 0..4095 chunks of 8 elems
            int row = cid >> 5, c = cid & 31;
            float4 v0 = __ldg(&xp[row * 64 + c * 2]);
            float4 v1 = __ldg(&xp[row * 64 + c * 2 + 1]);
            uint4 hv;
            hv.x = pack_h2(v0.x, v0.y);
            hv.y = pack_h2(v0.z, v0.w);
            hv.z = pack_h2(v1.x, v1.y);
            hv.w = pack_h2(v1.z, v1.w);
            uint32_t off = row * 512 + ((c ^ (row & 7)) << 4);
            *(uint4*)(smem + SM_A + off) = hv;
            xh_out[row * 32 + c] = hv;            // coalesced fp16 copy of x
        }
    }

    // ---- per-lane fragment address invariants ----
    int g = lid >> 2, t = lid & 3, r8 = lid & 7, j = lid >> 3;
    int arow = mw * 32 + (j & 1) * 8 + r8;
    uint32_t aoff0 = SM_A + arow * 512;
    int arm = arow & 7, ac0 = j >> 1;

    const float* smB1 = (const float*)(smem + SM_B1);
    const float* smW2 = (const float*)(smem + SM_W2);
    float part[4] = {0.f, 0.f, 0.f, 0.f};         // rows mw*32 + {g, g+8, 16+g, 24+g}

    __syncthreads();                              // A + constants staged

    for (int ch = 0; ch < 4; ch++) {
        const uint4* bp = g_bfrag + ((size_t)(nw * 4 + ch) * 16) * 64 + lid;

        float acc[2][4][4];
        #pragma unroll
        for (int a = 0; a < 2; a++)
            #pragma unroll
            for (int b = 0; b < 4; b++)
                #pragma unroll
                for (int cc = 0; cc < 4; cc++) acc[a][b][cc] = 0.f;

        #pragma unroll 8
        for (int ks = 0; ks < 16; ks++) {
            uint32_t sa = (uint32_t)(((2 * ks + ac0) ^ arm) << 4);
            uint32_t a0[4], a1[4];
            ldsm_x4(sb + aoff0 + sa,        a0[0], a0[1], a0[2], a0[3]);
            ldsm_x4(sb + aoff0 + 8192 + sa, a1[0], a1[1], a1[2], a1[3]);
            uint4 q0 = __ldg(bp + ks * 64);
            uint4 q1 = __ldg(bp + ks * 64 + 32);

            mma_f16(acc[0][0], a0[0], a0[1], a0[2], a0[3], q0.x, q0.y);
            mma_f16(acc[0][1], a0[0], a0[1], a0[2], a0[3], q0.z, q0.w);
            mma_f16(acc[0][2], a0[0], a0[1], a0[2], a0[3], q1.x, q1.y);
            mma_f16(acc[0][3], a0[0], a0[1], a0[2], a0[3], q1.z, q1.w);
            mma_f16(acc[1][0], a1[0], a1[1], a1[2], a1[3], q0.x, q0.y);
            mma_f16(acc[1][1], a1[0], a1[1], a1[2], a1[3], q0.z, q0.w);
            mma_f16(acc[1][2], a1[0], a1[1], a1[2], a1[3], q1.x, q1.y);
            mma_f16(acc[1][3], a1[0], a1[1], a1[2], a1[3], q1.z, q1.w);
        }

        // chunk epilogue: fold h -> relu(h + b1) . W2 into per-row partials
        int colb = ch * 64 + nw * 32 + 2 * t;
        #pragma unroll
        for (int nt = 0; nt < 4; nt++) {
            float bv0 = smB1[colb + nt * 8],     bv1 = smB1[colb + nt * 8 + 1];
            float wv0 = smW2[colb + nt * 8],     wv1 = smW2[colb + nt * 8 + 1];
            #pragma unroll
            for (int mt = 0; mt < 2; mt++) {
                part[mt * 2 + 0] += fmaxf(acc[mt][nt][0] + bv0, 0.f) * wv0
                                  + fmaxf(acc[mt][nt][1] + bv1, 0.f) * wv1;
                part[mt * 2 + 1] += fmaxf(acc[mt][nt][2] + bv0, 0.f) * wv0
                                  + fmaxf(acc[mt][nt][3] + bv1, 0.f) * wv1;
            }
        }
    }

    // reduce over the 4 lanes (t) that share each row
    #pragma unroll
    for (int p = 0; p < 4; p++) {
        part[p] += __shfl_xor_sync(0xffffffffu, part[p], 1);
        part[p] += __shfl_xor_sync(0xffffffffu, part[p], 2);
    }
    if (t == 0) {
        float* sc = (float*)(smem + SM_SC);
        atomicAdd(&sc[mw * 32 + g],      part[0]);
        atomicAdd(&sc[mw * 32 + 8 + g],  part[1]);
        atomicAdd(&sc[mw * 32 + 16 + g], part[2]);
        atomicAdd(&sc[mw * 32 + 24 + g], part[3]);
    }
    __syncthreads();
    if (tid < 128)
        g_scores[rowbase + tid] = ((float*)(smem + SM_SC))[tid] + __ldg(b2);
}

// ---------------- kernel 3: pooling, cp.async, 32-row sub-batches ------------
// dynamic smem: [0,16384) xbuf0, [16384,32768) xbuf1, [32768,+4096) wbuf,
// [36864,+1024) red, [37888,+8192) accs[8][256]  -> total 46080 (4 CTAs/SM)
#define P_WB   32768
#define P_RED  36864
#define P_ACC  37888
#define SMEM_POOL_TOTAL 46080

__global__ void __launch_bounds__(256, 4)
k_pool(float* __restrict__ out) {
    extern __shared__ char ps[];
    uint32_t sbp = smem_u32(ps);
    float* wbuf = (float*)(ps + P_WB);
    float* red  = (float*)(ps + P_RED);
    float* accs = (float*)(ps + P_ACC);   // [8][256]
    int g = blockIdx.x, t = threadIdx.x;
    int rg = t >> 5, cl = t & 31;
    int s0 = g_segstart[g], s1 = g_segstart[g + 1];

    // segment max, clamped at >= 0 (scatter-amax-into-zeros semantics)
    float m = 0.f;
    for (int i = s0 + t; i < s1; i += 256) m = fmaxf(m, g_scores[i]);
    red[t] = m; __syncthreads();
    #pragma unroll
    for (int st = 128; st > 0; st >>= 1) {
        if (t < st) red[t] = fmaxf(red[t], red[t + st]);
        __syncthreads();
    }
    m = red[0]; __syncthreads();

    float den = 0.f;
    float ac[8] = {0.f, 0.f, 0.f, 0.f, 0.f, 0.f, 0.f, 0.f};
    const char* xbytes = (const char*)g_xh;

    for (int base = s0; base < s1; base += 1024) {
        int n = min(1024, s1 - base);
        for (int i = t; i < n; i += 256) {
            float e = __expf(g_scores[base + i] - m);
            wbuf[i] = e;
            den += e;
        }
        __syncthreads();                          // wbuf visible; prev buffers free

        int nsub = (n + 31) >> 5;                 // 32-row sub-batches
        {
            int cnt = min(32, n) * 32;            // 16B units
            const char* src = xbytes + (size_t)base * 512;
            for (int idx = t; idx < cnt; idx += 256)
                cp16(sbp + idx * 16, src + (size_t)idx * 16);
            CP_COMMIT();
        }
        for (int s = 0; s < nsub; s++) {
            if (s > 0) __syncthreads();           // consumers of buf (s+1)&1 done
            if (s + 1 < nsub) {
                int r0n = (s + 1) * 32;
                int cnt = min(32, n - r0n) * 32;
                const char* src = xbytes + (size_t)(base + r0n) * 512;
                uint32_t dst = sbp + ((s + 1) & 1) * 16384;
                for (int idx = t; idx < cnt; idx += 256)
                    cp16(dst + idx * 16, src + (size_t)idx * 16);
                CP_COMMIT();
                CP_WAIT(1);
            } else {
                CP_WAIT(0);
            }
            __syncthreads();                      // buf s&1 data visible to all

            int r0 = s * 32;
            int cnt = min(32, n - r0);
            uint32_t buf = sbp + (s & 1) * 16384 + cl * 16;
            for (int i = rg; i < cnt; i += 8) {
                float w = wbuf[r0 + i];
                uint32_t q0, q1, q2, q3;
                asm volatile("ld.shared.v4.u32 {%0,%1,%2,%3}, [%4];"
                             : "=r"(q0), "=r"(q1), "=r"(q2), "=r"(q3)
                             : "r"(buf + (uint32_t)i * 512));
                float2 p;
                p = __half22float2(*(__half2*)&q0);
                ac[0] = fmaf(p.x, w, ac[0]); ac[1] = fmaf(p.y, w, ac[1]);
                p = __half22float2(*(__half2*)&q1);
                ac[2] = fmaf(p.x, w, ac[2]); ac[3] = fmaf(p.y, w, ac[3]);
                p = __half22float2(*(__half2*)&q2);
                ac[4] = fmaf(p.x, w, ac[4]); ac[5] = fmaf(p.y, w, ac[5]);
                p = __half22float2(*(__half2*)&q3);
                ac[6] = fmaf(p.x, w, ac[6]); ac[7] = fmaf(p.y, w, ac[7]);
            }
        }
        __syncthreads();                          // batch done before wbuf reuse
    }

    // reduce denominator
    red[t] = den; __syncthreads();
    #pragma unroll
    for (int st = 128; st > 0; st >>= 1) {
        if (t < st) red[t] += red[t + st];
        __syncthreads();
    }
    den = red[0] + 1e-9f;
    __syncthreads();

    // combine row-group partials
    #pragma unroll
    for (int h = 0; h < 8; h++) accs[rg * 256 + cl * 8 + h] = ac[h];
    __syncthreads();
    float s = 0.f;
    #pragma unroll
    for (int r = 0; r < 8; r++) s += accs[r * 256 + t];
    out[g * 256 + t] = s / den;
}

// ---------------- launch ----------------------------------------------------
extern "C" void kernel_launch(void* const* d_in, const int* in_sizes, int n_in,
                              void* d_out, int out_size) {
    const float* x = 0; const float* W1 = 0; const float* b1 = 0;
    const float* W2 = 0; const float* b2 = 0; const void* batch = 0;
    for (int i = 0; i < n_in; i++) {
        switch (in_sizes[i]) {
            case 67108864: x = (const float*)d_in[i]; break;
            case 65536:    W1 = (const float*)d_in[i]; break;
            case 262144:   batch = d_in[i]; break;
            case 1:        b2 = (const float*)d_in[i]; break;
            case 256:
                if (!b1) b1 = (const float*)d_in[i];
                else     W2 = (const float*)d_in[i];
                break;
            default: break;
        }
    }
    if (!x)     x     = (const float*)d_in[0];
    if (!W1)    W1    = (const float*)d_in[1];
    if (!b1)    b1    = (const float*)d_in[2];
    if (!W2)    W2    = (const float*)d_in[3];
    if (!b2)    b2    = (const float*)d_in[4];
    if (!batch) batch = d_in[5];

    cudaFuncSetAttribute(k_scores, cudaFuncAttributeMaxDynamicSharedMemorySize,
                         SMEM_SCORES_TOTAL);
    cudaFuncSetAttribute(k_pool, cudaFuncAttributeMaxDynamicSharedMemorySize,
                         SMEM_POOL_TOTAL);

    k_prep<<<1028, 256>>>(W1, batch);
    k_scores<<<NROWS / 128, 256, SMEM_SCORES_TOTAL>>>(x, b1, W2, b2);
    k_pool<<<NSEG, 256, SMEM_POOL_TOTAL>>>((float*)d_out);
}